// round 1
// baseline (speedup 1.0000x reference)
#include <cuda_runtime.h>
#include <cstddef>

#define N_ROWS     131072
#define D_IN       512
#define D_H        1024
#define D_OUT      128
#define NUM_GROUPS 1024
#define LN_EPS     1e-5f

// ---------------- scratch (device globals: allocation-free rule) -------------
__device__ float g_h1[(size_t)N_ROWS * D_H];   // 512 MB
__device__ float g_h2[(size_t)N_ROWS * D_H];   // 512 MB
__device__ float g_y [(size_t)N_ROWS * D_OUT]; //  64 MB

// ---------------- SGEMM: C = act(A[M,K] @ B[K,Ncols] + bias) ----------------
// 128x128 tile, BK=16, 256 threads, 8x8 per thread.
__global__ __launch_bounds__(256, 2)
void sgemm_bias_act(const float* __restrict__ A, const float* __restrict__ B,
                    const float* __restrict__ bias, float* __restrict__ C,
                    int K, int Ncols, int do_relu)
{
    __shared__ float As[16][128];
    __shared__ float Bs[16][128];

    const int tid = threadIdx.x;
    const int tx  = tid & 15;       // col group (8 cols)
    const int ty  = tid >> 4;       // row group (8 rows)
    const int row0 = blockIdx.y * 128;
    const int col0 = blockIdx.x * 128;

    // A-tile load mapping: 128 rows x 16 k, float4 along K
    const int ar  = tid & 127;
    const int akq = (tid >> 7) * 8;          // 0 or 8
    // B-tile load mapping: 16 k x 128 cols, float4 along cols
    const int bkr = tid >> 5;                // 0..7
    const int bc  = (tid & 31) * 4;          // 0..124

    const float* Aptr = A + (size_t)(row0 + ar) * K + akq;
    const float* Bptr = B + (size_t)bkr * Ncols + col0 + bc;

    float acc[8][8];
#pragma unroll
    for (int i = 0; i < 8; i++)
#pragma unroll
        for (int j = 0; j < 8; j++) acc[i][j] = 0.f;

    for (int k0 = 0; k0 < K; k0 += 16) {
        float4 a0 = *(const float4*)(Aptr + k0);
        float4 a1 = *(const float4*)(Aptr + k0 + 4);
        float4 b0 = *(const float4*)(Bptr + (size_t)k0 * Ncols);
        float4 b1 = *(const float4*)(Bptr + (size_t)(k0 + 8) * Ncols);

        __syncthreads();   // previous iteration's readers done
        As[akq + 0][ar] = a0.x; As[akq + 1][ar] = a0.y;
        As[akq + 2][ar] = a0.z; As[akq + 3][ar] = a0.w;
        As[akq + 4][ar] = a1.x; As[akq + 5][ar] = a1.y;
        As[akq + 6][ar] = a1.z; As[akq + 7][ar] = a1.w;
        *(float4*)&Bs[bkr][bc]     = b0;
        *(float4*)&Bs[bkr + 8][bc] = b1;
        __syncthreads();

#pragma unroll
        for (int k = 0; k < 16; k++) {
            float4 av0 = *(const float4*)&As[k][ty * 8];
            float4 av1 = *(const float4*)&As[k][ty * 8 + 4];
            float4 bv0 = *(const float4*)&Bs[k][tx * 8];
            float4 bv1 = *(const float4*)&Bs[k][tx * 8 + 4];
            float a[8] = {av0.x, av0.y, av0.z, av0.w, av1.x, av1.y, av1.z, av1.w};
            float b[8] = {bv0.x, bv0.y, bv0.z, bv0.w, bv1.x, bv1.y, bv1.z, bv1.w};
#pragma unroll
            for (int i = 0; i < 8; i++)
#pragma unroll
                for (int j = 0; j < 8; j++)
                    acc[i][j] += a[i] * b[j];
        }
    }

    float bv[8];
#pragma unroll
    for (int j = 0; j < 8; j++) bv[j] = bias[col0 + tx * 8 + j];

#pragma unroll
    for (int i = 0; i < 8; i++) {
        const int r = row0 + ty * 8 + i;
        float v[8];
#pragma unroll
        for (int j = 0; j < 8; j++) {
            float c = acc[i][j] + bv[j];
            if (do_relu) c = fmaxf(c, 0.f);
            v[j] = c;
        }
        float4* dst = (float4*)&C[(size_t)r * Ncols + col0 + tx * 8];
        dst[0] = make_float4(v[0], v[1], v[2], v[3]);
        dst[1] = make_float4(v[4], v[5], v[6], v[7]);
    }
}

// ---------------- LayerNorm (in place, D=1024, one row per block) -----------
__global__ __launch_bounds__(256)
void layernorm_inplace(float* __restrict__ X, const float* __restrict__ gamma,
                       const float* __restrict__ beta)
{
    const int row = blockIdx.x;
    float* xr = X + (size_t)row * D_H;
    const int t = threadIdx.x;            // 256 threads, 4 elems each

    float4 v = *(const float4*)(xr + t * 4);
    float s  = v.x + v.y + v.z + v.w;
    float ss = v.x * v.x + v.y * v.y + v.z * v.z + v.w * v.w;

#pragma unroll
    for (int o = 16; o > 0; o >>= 1) {
        s  += __shfl_xor_sync(0xFFFFFFFFu, s,  o);
        ss += __shfl_xor_sync(0xFFFFFFFFu, ss, o);
    }
    __shared__ float ws[8], wss[8];
    const int w = t >> 5, l = t & 31;
    if (l == 0) { ws[w] = s; wss[w] = ss; }
    __syncthreads();
    if (w == 0) {
        s  = (l < 8) ? ws[l]  : 0.f;
        ss = (l < 8) ? wss[l] : 0.f;
#pragma unroll
        for (int o = 4; o > 0; o >>= 1) {
            s  += __shfl_xor_sync(0xFFFFFFFFu, s,  o);
            ss += __shfl_xor_sync(0xFFFFFFFFu, ss, o);
        }
        if (l == 0) { ws[0] = s; wss[0] = ss; }
    }
    __syncthreads();
    const float inv = 1.f / (float)D_H;
    const float mu  = ws[0] * inv;
    const float var = fmaxf(wss[0] * inv - mu * mu, 0.f);
    const float rs  = rsqrtf(var + LN_EPS);

    float4 gv = *(const float4*)(gamma + t * 4);
    float4 bv = *(const float4*)(beta  + t * 4);
    v.x = (v.x - mu) * rs * gv.x + bv.x;
    v.y = (v.y - mu) * rs * gv.y + bv.y;
    v.z = (v.z - mu) * rs * gv.z + bv.z;
    v.w = (v.w - mu) * rs * gv.w + bv.w;
    *(float4*)(xr + t * 4) = v;
}

// ---------------- deterministic segment mean --------------------------------
// One block per group, 128 threads (one per output column).
// Deterministic: index list built with per-thread prefix offsets (no atomics),
// summed in fixed list order -> bit-stable across graph replays.
#define SEG_CAP 4096
__global__ __launch_bounds__(128)
void segment_mean(const float* __restrict__ y, const int* __restrict__ batch,
                  float* __restrict__ out)
{
    const int g = blockIdx.x;
    const int t = threadIdx.x;

    __shared__ int s_cnt[128];
    __shared__ int s_idx[SEG_CAP];
    __shared__ int s_total;

    int cnt = 0;
    for (int i = t; i < N_ROWS; i += 128)
        cnt += (batch[i] == g) ? 1 : 0;
    s_cnt[t] = cnt;
    __syncthreads();

    int off = 0;
    for (int u = 0; u < t; u++) off += s_cnt[u];
    if (t == 127) s_total = off + cnt;
    __syncthreads();
    const int total = s_total;

    int o = off;
    for (int i = t; i < N_ROWS; i += 128) {
        if (batch[i] == g) {
            if (o < SEG_CAP) s_idx[o] = i;
            o++;
        }
    }
    __syncthreads();

    float acc = 0.f;
    const int m = total < SEG_CAP ? total : SEG_CAP;
    for (int j = 0; j < m; j++)
        acc += y[(size_t)s_idx[j] * D_OUT + t];

    out[g * D_OUT + t] = (total > 0) ? acc / (float)total : 0.f;
}

// ---------------- launch -----------------------------------------------------
extern "C" void kernel_launch(void* const* d_in, const int* in_sizes, int n_in,
                              void* d_out, int out_size)
{
    const float* X   = (const float*)d_in[0];
    const float* W1  = (const float*)d_in[1];
    const float* b1  = (const float*)d_in[2];
    const float* g1  = (const float*)d_in[3];
    const float* be1 = (const float*)d_in[4];
    const float* W2  = (const float*)d_in[5];
    const float* b2  = (const float*)d_in[6];
    const float* g2  = (const float*)d_in[7];
    const float* be2 = (const float*)d_in[8];
    const float* W3  = (const float*)d_in[9];
    const float* b3  = (const float*)d_in[10];
    const int*   ab  = (const int*)d_in[11];
    float* out = (float*)d_out;

    float *h1, *h2, *y;
    cudaGetSymbolAddress((void**)&h1, g_h1);
    cudaGetSymbolAddress((void**)&h2, g_h2);
    cudaGetSymbolAddress((void**)&y,  g_y);

    dim3 blk(256);
    sgemm_bias_act<<<dim3(D_H / 128, N_ROWS / 128), blk>>>(X,  W1, b1, h1, D_IN, D_H, 1);
    layernorm_inplace<<<N_ROWS, 256>>>(h1, g1, be1);
    sgemm_bias_act<<<dim3(D_H / 128, N_ROWS / 128), blk>>>(h1, W2, b2, h2, D_H, D_H, 1);
    layernorm_inplace<<<N_ROWS, 256>>>(h2, g2, be2);
    sgemm_bias_act<<<dim3(D_OUT / 128, N_ROWS / 128), blk>>>(h2, W3, b3, y, D_H, D_OUT, 0);
    segment_mean<<<NUM_GROUPS, 128>>>(y, ab, out);
}

// round 3
// speedup vs baseline: 2.6282x; 2.6282x over previous
#include <cuda_runtime.h>
#include <cuda_bf16.h>
#include <cstdint>
#include <cstddef>

#define N_ROWS     131072
#define D_IN       512
#define D_H        1024
#define D_OUT      128
#define NUM_GROUPS 1024
#define LN_EPS     1e-5f

// ---------------- scratch (device globals: allocation-free rule) -------------
__device__ __nv_bfloat16 g_bufA[(size_t)N_ROWS * 2048];     // hi|lo expanded A
__device__ float         g_h  [(size_t)N_ROWS * D_H];       // fp32 hidden
__device__ float         g_y  [(size_t)N_ROWS * D_OUT];
__device__ __nv_bfloat16 g_Bt1[(size_t)D_H   * (3 * D_IN)]; // [1024, 1536]
__device__ __nv_bfloat16 g_Bt2[(size_t)D_H   * (3 * D_H)];  // [1024, 3072]
__device__ __nv_bfloat16 g_Bt3[(size_t)D_OUT * (3 * D_H)];  // [128, 3072]

// ======================= helpers ============================================
__device__ __forceinline__ uint32_t smem_u32(const void* p) {
    uint32_t a;
    asm("{ .reg .u64 t; cvta.to.shared.u64 t, %1; cvt.u32.u64 %0, t; }" : "=r"(a) : "l"(p));
    return a;
}
__device__ __forceinline__ uint32_t sw128(uint32_t b) { return b ^ ((b >> 3) & 0x70); }
__device__ __forceinline__ void cp_async16(uint32_t dst, const void* src) {
    asm volatile("cp.async.cg.shared.global [%0], [%1], 16;" :: "r"(dst), "l"(src) : "memory");
}
__device__ __forceinline__ void ldsm_x4(uint32_t* r, uint32_t addr) {
    asm volatile("ldmatrix.sync.aligned.m8n8.x4.shared.b16 {%0,%1,%2,%3}, [%4];"
                 : "=r"(r[0]), "=r"(r[1]), "=r"(r[2]), "=r"(r[3]) : "r"(addr));
}
__device__ __forceinline__ void mma_bf16(float* c, const uint32_t* a, uint32_t b0, uint32_t b1) {
    asm volatile(
        "mma.sync.aligned.m16n8k16.row.col.f32.bf16.bf16.f32 "
        "{%0,%1,%2,%3}, {%4,%5,%6,%7}, {%8,%9}, {%0,%1,%2,%3};"
        : "+f"(c[0]), "+f"(c[1]), "+f"(c[2]), "+f"(c[3])
        : "r"(a[0]), "r"(a[1]), "r"(a[2]), "r"(a[3]), "r"(b0), "r"(b1));
}

// ======================= mma.sync split-bf16 GEMM ===========================
// C[M, Ncols] = act(A2 @ Bt^T + bias); A2 = [M, lda] bf16 (hi|lo),
// Bt = [Ncols, ldb] bf16 (hi|hi|lo along k'), k' in [0, 3K).
#define BM 128
#define BN 128
#define BK 64
#define STAGES 3
#define STAGE_BYTES (BM * 128 + BN * 128)   // 32 KB

__global__ void __launch_bounds__(256, 2)
gemm_mma(const __nv_bfloat16* __restrict__ A, const __nv_bfloat16* __restrict__ Bt,
         const float* __restrict__ bias, float* __restrict__ C,
         int K, int lda, int ldb, int Ncols, int do_relu)
{
    extern __shared__ __align__(1024) char smem[];
    const uint32_t sbase = smem_u32(smem);
    const int tid = threadIdx.x, lane = tid & 31, wid = tid >> 5;
    const int wm = wid & 3, wn = wid >> 2;                 // 4 x 2 warp grid
    const int m0 = blockIdx.y * BM, n0 = blockIdx.x * BN;
    const int K2 = 2 * K;
    const int NC = (3 * K) / BK;

    auto fill = [&](int ci, int s) {
        const int kp = ci * BK;
        const int ka = (kp < K2) ? kp : (kp - K2);         // term3 reuses A-hi
        const uint32_t sA = sbase + s * STAGE_BYTES;
        const uint32_t sB = sA + BM * 128;
#pragma unroll
        for (int j = 0; j < 4; j++) {
            const int c = tid + j * 256;
            const int r = c >> 3, col = (c & 7) * 16;
            cp_async16(sA + sw128(r * 128 + col),
                       (const char*)(A + (size_t)(m0 + r) * lda + ka) + col);
        }
#pragma unroll
        for (int j = 0; j < 4; j++) {
            const int c = tid + j * 256;
            const int r = c >> 3, col = (c & 7) * 16;
            cp_async16(sB + sw128(r * 128 + col),
                       (const char*)(Bt + (size_t)(n0 + r) * ldb + kp) + col);
        }
        asm volatile("cp.async.commit_group;" ::: "memory");
    };

    float acc[2][8][4];
#pragma unroll
    for (int i = 0; i < 2; i++)
#pragma unroll
        for (int j = 0; j < 8; j++)
#pragma unroll
            for (int r = 0; r < 4; r++) acc[i][j][r] = 0.f;

    for (int j = 0; j < STAGES; j++) fill(j, j);

    for (int i = 0; i < NC; i++) {
        const int s = i % STAGES;
        asm volatile("cp.async.wait_group %0;" :: "n"(STAGES - 1) : "memory");
        __syncthreads();
        const uint32_t sA = sbase + s * STAGE_BYTES;
        const uint32_t sB = sA + BM * 128;

#pragma unroll
        for (int k16 = 0; k16 < BK / 16; k16++) {
            const uint32_t kb = k16 * 32 + (lane >> 4) * 16;
            uint32_t a[2][4];
#pragma unroll
            for (int mt = 0; mt < 2; mt++) {
                const int r = wm * 32 + mt * 16 + (lane & 15);
                ldsm_x4(a[mt], sA + sw128(r * 128 + kb));
            }
            uint32_t b[4][4];
#pragma unroll
            for (int nt2 = 0; nt2 < 4; nt2++) {
                const int r = wn * 64 + nt2 * 16 + (lane & 15);
                ldsm_x4(b[nt2], sB + sw128(r * 128 + kb));
            }
#pragma unroll
            for (int mt = 0; mt < 2; mt++)
#pragma unroll
                for (int nt = 0; nt < 8; nt++)
                    mma_bf16(acc[mt][nt], a[mt], b[nt >> 1][nt & 1], b[nt >> 1][2 + (nt & 1)]);
        }
        __syncthreads();
        if (i + STAGES < NC) fill(i + STAGES, s);
    }

    // epilogue: bias + relu, fp32 stores
#pragma unroll
    for (int mt = 0; mt < 2; mt++) {
#pragma unroll
        for (int nt = 0; nt < 8; nt++) {
            const int col = n0 + wn * 64 + nt * 8 + (lane & 3) * 2;
            const float b0 = bias[col], b1 = bias[col + 1];
            const int r0 = m0 + wm * 32 + mt * 16 + (lane >> 2);
            float v0 = acc[mt][nt][0] + b0, v1 = acc[mt][nt][1] + b1;
            float v2 = acc[mt][nt][2] + b0, v3 = acc[mt][nt][3] + b1;
            if (do_relu) {
                v0 = fmaxf(v0, 0.f); v1 = fmaxf(v1, 0.f);
                v2 = fmaxf(v2, 0.f); v3 = fmaxf(v3, 0.f);
            }
            *(float2*)(C + (size_t)r0 * Ncols + col)       = make_float2(v0, v1);
            *(float2*)(C + (size_t)(r0 + 8) * Ncols + col) = make_float2(v2, v3);
        }
    }
}

// =================== operand prep kernels ===================================
__device__ __forceinline__ void split_bf16(float x, __nv_bfloat16& hi, __nv_bfloat16& lo) {
    hi = __float2bfloat16_rn(x);
    lo = __float2bfloat16_rn(x - __bfloat162float(hi));
}

// X [N, 512] f32 -> bufA [N, 1024] bf16 (hi | lo)
__global__ void __launch_bounds__(256)
convertX(const float* __restrict__ X, __nv_bfloat16* __restrict__ out)
{
    const size_t i4 = ((size_t)blockIdx.x * 256 + threadIdx.x) * 4;
    if (i4 >= (size_t)N_ROWS * D_IN) return;
    const size_t r = i4 / D_IN, c = i4 % D_IN;
    float4 v = *(const float4*)(X + i4);
    __nv_bfloat16 h[4], l[4];
    split_bf16(v.x, h[0], l[0]); split_bf16(v.y, h[1], l[1]);
    split_bf16(v.z, h[2], l[2]); split_bf16(v.w, h[3], l[3]);
    __nv_bfloat16* oh = out + r * 1024 + c;
    __nv_bfloat16* ol = out + r * 1024 + D_IN + c;
    *(__nv_bfloat162*)(oh)     = __nv_bfloat162(h[0], h[1]);
    *(__nv_bfloat162*)(oh + 2) = __nv_bfloat162(h[2], h[3]);
    *(__nv_bfloat162*)(ol)     = __nv_bfloat162(l[0], l[1]);
    *(__nv_bfloat162*)(ol + 2) = __nv_bfloat162(l[2], l[3]);
}

// W [K, Ncols] f32 -> Bt [Ncols, 3K] bf16 = (hi | hi | lo)
__global__ void __launch_bounds__(256)
convertW(const float* __restrict__ W, __nv_bfloat16* __restrict__ Bt, int K, int Ncols)
{
    const size_t i = (size_t)blockIdx.x * 256 + threadIdx.x;
    if (i >= (size_t)K * Ncols) return;
    const int n = (int)(i % Ncols), k = (int)(i / Ncols);
    __nv_bfloat16 h, l;
    split_bf16(W[(size_t)k * Ncols + n], h, l);
    __nv_bfloat16* row = Bt + (size_t)n * (3 * K);
    row[k] = h; row[K + k] = h; row[2 * K + k] = l;
}

// LayerNorm(h fp32 [N,1024]) -> bufA [N, 2048] bf16 (hi | lo)
__global__ void __launch_bounds__(256)
ln_convert(const float* __restrict__ H, const float* __restrict__ gamma,
           const float* __restrict__ beta, __nv_bfloat16* __restrict__ out)
{
    const int row = blockIdx.x;
    const float* xr = H + (size_t)row * D_H;
    const int t = threadIdx.x;

    float4 v = *(const float4*)(xr + t * 4);
    float s = v.x + v.y + v.z + v.w;
    float ss = v.x * v.x + v.y * v.y + v.z * v.z + v.w * v.w;
#pragma unroll
    for (int o = 16; o > 0; o >>= 1) {
        s  += __shfl_xor_sync(0xFFFFFFFFu, s,  o);
        ss += __shfl_xor_sync(0xFFFFFFFFu, ss, o);
    }
    __shared__ float ws[8], wss[8];
    const int w = t >> 5, l = t & 31;
    if (l == 0) { ws[w] = s; wss[w] = ss; }
    __syncthreads();
    if (w == 0) {
        s  = (l < 8) ? ws[l]  : 0.f;
        ss = (l < 8) ? wss[l] : 0.f;
#pragma unroll
        for (int o = 4; o > 0; o >>= 1) {
            s  += __shfl_xor_sync(0xFFFFFFFFu, s,  o);
            ss += __shfl_xor_sync(0xFFFFFFFFu, ss, o);
        }
        if (l == 0) { ws[0] = s; wss[0] = ss; }
    }
    __syncthreads();
    const float inv = 1.f / (float)D_H;
    const float mu  = ws[0] * inv;
    const float var = fmaxf(wss[0] * inv - mu * mu, 0.f);
    const float rs  = rsqrtf(var + LN_EPS);

    float4 gv = *(const float4*)(gamma + t * 4);
    float4 bv = *(const float4*)(beta  + t * 4);
    float n0 = (v.x - mu) * rs * gv.x + bv.x;
    float n1 = (v.y - mu) * rs * gv.y + bv.y;
    float n2 = (v.z - mu) * rs * gv.z + bv.z;
    float n3 = (v.w - mu) * rs * gv.w + bv.w;
    __nv_bfloat16 h[4], lo[4];
    split_bf16(n0, h[0], lo[0]); split_bf16(n1, h[1], lo[1]);
    split_bf16(n2, h[2], lo[2]); split_bf16(n3, h[3], lo[3]);
    __nv_bfloat16* oh = out + (size_t)row * 2048 + t * 4;
    __nv_bfloat16* ol = oh + D_H;
    *(__nv_bfloat162*)(oh)     = __nv_bfloat162(h[0], h[1]);
    *(__nv_bfloat162*)(oh + 2) = __nv_bfloat162(h[2], h[3]);
    *(__nv_bfloat162*)(ol)     = __nv_bfloat162(lo[0], lo[1]);
    *(__nv_bfloat162*)(ol + 2) = __nv_bfloat162(lo[2], lo[3]);
}

// ---------------- deterministic segment mean --------------------------------
#define SEG_CAP 4096
__global__ void __launch_bounds__(128)
segment_mean(const float* __restrict__ y, const int* __restrict__ batch,
             float* __restrict__ out)
{
    const int g = blockIdx.x;
    const int t = threadIdx.x;

    __shared__ int s_cnt[128];
    __shared__ int s_idx[SEG_CAP];
    __shared__ int s_total;

    int cnt = 0;
    for (int i = t; i < N_ROWS; i += 128)
        cnt += (batch[i] == g) ? 1 : 0;
    s_cnt[t] = cnt;
    __syncthreads();

    int off = 0;
    for (int u = 0; u < t; u++) off += s_cnt[u];
    if (t == 127) s_total = off + cnt;
    __syncthreads();
    const int total = s_total;

    int o = off;
    for (int i = t; i < N_ROWS; i += 128) {
        if (batch[i] == g) {
            if (o < SEG_CAP) s_idx[o] = i;
            o++;
        }
    }
    __syncthreads();

    float acc = 0.f;
    const int m = total < SEG_CAP ? total : SEG_CAP;
    for (int j = 0; j < m; j++)
        acc += y[(size_t)s_idx[j] * D_OUT + t];

    out[g * D_OUT + t] = (total > 0) ? acc / (float)total : 0.f;
}

// ---------------- launch -----------------------------------------------------
extern "C" void kernel_launch(void* const* d_in, const int* in_sizes, int n_in,
                              void* d_out, int out_size)
{
    const float* X   = (const float*)d_in[0];
    const float* W1  = (const float*)d_in[1];
    const float* b1  = (const float*)d_in[2];
    const float* g1  = (const float*)d_in[3];
    const float* be1 = (const float*)d_in[4];
    const float* W2  = (const float*)d_in[5];
    const float* b2  = (const float*)d_in[6];
    const float* g2  = (const float*)d_in[7];
    const float* be2 = (const float*)d_in[8];
    const float* W3  = (const float*)d_in[9];
    const float* b3  = (const float*)d_in[10];
    const int*   ab  = (const int*)d_in[11];
    float* out = (float*)d_out;

    __nv_bfloat16 *bufA, *Bt1, *Bt2, *Bt3;
    float *h, *y;
    cudaGetSymbolAddress((void**)&bufA, g_bufA);
    cudaGetSymbolAddress((void**)&h,    g_h);
    cudaGetSymbolAddress((void**)&y,    g_y);
    cudaGetSymbolAddress((void**)&Bt1,  g_Bt1);
    cudaGetSymbolAddress((void**)&Bt2,  g_Bt2);
    cudaGetSymbolAddress((void**)&Bt3,  g_Bt3);

    const int SMEM = STAGES * STAGE_BYTES;   // 96 KB
    static bool attr_set = false;
    if (!attr_set) {
        cudaFuncSetAttribute(gemm_mma, cudaFuncAttributeMaxDynamicSharedMemorySize, SMEM);
        attr_set = true;
    }

    // operand prep
    convertW<<<(D_IN * D_H + 255) / 256, 256>>>(W1, Bt1, D_IN, D_H);
    convertW<<<(D_H * D_H + 255) / 256, 256>>>(W2, Bt2, D_H, D_H);
    convertW<<<(D_H * D_OUT + 255) / 256, 256>>>(W3, Bt3, D_H, D_OUT);
    convertX<<<(int)(((size_t)N_ROWS * D_IN / 4 + 255) / 256), 256>>>(X, bufA);

    // layer 1: [N,512] @ [512,1024]
    gemm_mma<<<dim3(D_H / BN, N_ROWS / BM), 256, SMEM>>>(
        bufA, Bt1, b1, h, D_IN, 2 * D_IN, 3 * D_IN, D_H, 1);
    ln_convert<<<N_ROWS, 256>>>(h, g1, be1, bufA);

    // layer 2: [N,1024] @ [1024,1024]
    gemm_mma<<<dim3(D_H / BN, N_ROWS / BM), 256, SMEM>>>(
        bufA, Bt2, b2, h, D_H, 2 * D_H, 3 * D_H, D_H, 1);
    ln_convert<<<N_ROWS, 256>>>(h, g2, be2, bufA);

    // layer 3: [N,1024] @ [1024,128]
    gemm_mma<<<dim3(D_OUT / BN, N_ROWS / BM), 256, SMEM>>>(
        bufA, Bt3, b3, y, D_H, 2 * D_H, 3 * D_H, D_OUT, 0);

    segment_mean<<<NUM_GROUPS, 128>>>(y, ab, out);
}